// round 8
// baseline (speedup 1.0000x reference)
#include <cuda_runtime.h>
#include <math.h>

#define HEADS 8
#define DIM 64
#define DH 64
#define DK 24
#define DHK 3
#define B 4
#define H 128
#define W 128
#define NTOK (H*W)           // 16384

typedef unsigned long long ull;

// ---------------- scratch ---------------------------------------------------
__device__ __align__(16) float g_kinp[B * DK * H * W];  // planar [b][ch][y][x]
__device__ __align__(16) float g_t1[B * DK * H * W];    // gelu(conv1) planar
__device__ __align__(16) float g_SW[2 * B * 24 * 64];   // S then W2
__device__ __align__(16) float g_wt[2][1728];           // transposed conv w

// ---------------- packed f32x2 helpers -------------------------------------
__device__ __forceinline__ ull pack2(float lo, float hi) {
    ull r; asm("mov.b64 %0, {%1,%2};" : "=l"(r) : "f"(lo), "f"(hi)); return r;
}
__device__ __forceinline__ void unpack2(ull v, float& lo, float& hi) {
    asm("mov.b64 {%0,%1}, %2;" : "=f"(lo), "=f"(hi) : "l"(v));
}
__device__ __forceinline__ void fma2(ull& d, ull a, ull b) {
    asm("fma.rn.f32x2 %0, %1, %2, %0;" : "+l"(d) : "l"(a), "l"(b));
}

__device__ __forceinline__ float gelu_exact(float x) {
    return 0.5f * x * (1.0f + erff(x * 0.70710678118654752f));
}

// ===========================================================================
// KWT: zero g_SW + transpose conv weights -> g_wt[(i*9+r)*24 + oc]
// ===========================================================================
__global__ __launch_bounds__(256) void kwt_prep(
    const float* __restrict__ c1w, const float* __restrict__ c2w)
{
    const int tid = threadIdx.x;
    for (int i = tid; i < 12288; i += 256) g_SW[i] = 0.f;
    for (int i = tid; i < 1728; i += 256) {
        int oc = i / 72, r2 = i - oc * 72;
        g_wt[0][r2 * 24 + oc] = c1w[i];
        g_wt[1][r2 * 24 + oc] = c2w[i];
    }
}

// ===========================================================================
// K1: k_inp = illu_map @ Wk (planar write) + S[b] += k_inp^T @ x
// grid (128 rows, B) block 256.
// ===========================================================================
__global__ __launch_bounds__(256, 4) void k1_kinp_S(
    const float* __restrict__ x, const float* __restrict__ im,
    const float* __restrict__ Wk)
{
    __shared__ __align__(16) float wk_s[576];
    __shared__ __align__(16) float k_s[128 * 25];
    __shared__ __align__(16) float buf[128 * 64];   // im_s then x_s

    const int tid = threadIdx.x;
    const int b = blockIdx.y;
    const int row = blockIdx.x;
    const int t0 = b * NTOK + row * 128;

    for (int i = tid; i < 576; i += 256) wk_s[i] = Wk[i];
    {
        const float* img = im + (size_t)t0 * 24;
        #pragma unroll
        for (int i = tid; i < 3072; i += 256) {
            int tok = i / 24, ci = i - tok * 24;
            buf[tok * 25 + ci] = img[i];
        }
    }
    __syncthreads();

    {
        const int tok = tid >> 1;
        const int j0 = (tid & 1) * 12;
        float acc[12];
        #pragma unroll
        for (int j = 0; j < 12; j++) acc[j] = 0.f;
        #pragma unroll 4
        for (int ci = 0; ci < 24; ci++) {
            float inv = buf[tok * 25 + ci];
            const float4* wp4 = (const float4*)&wk_s[ci * 24 + j0];
            float4 w0 = wp4[0], w1 = wp4[1], w2 = wp4[2];
            acc[0] += inv * w0.x; acc[1] += inv * w0.y; acc[2] += inv * w0.z; acc[3] += inv * w0.w;
            acc[4] += inv * w1.x; acc[5] += inv * w1.y; acc[6] += inv * w1.z; acc[7] += inv * w1.w;
            acc[8] += inv * w2.x; acc[9] += inv * w2.y; acc[10] += inv * w2.z; acc[11] += inv * w2.w;
        }
        #pragma unroll
        for (int j = 0; j < 12; j++) k_s[tok * 25 + j0 + j] = acc[j];
    }
    __syncthreads();

    {
        const float4* xg = (const float4*)(x + (size_t)t0 * 64);
        float4* xs4 = (float4*)buf;
        #pragma unroll
        for (int i = tid; i < 2048; i += 256) xs4[i] = xg[i];
    }
    {
        #pragma unroll
        for (int i = tid; i < 3072; i += 256) {
            int ch = i >> 7, xx = i & 127;
            g_kinp[(((size_t)b * 24 + ch) * H + row) * W + xx] = k_s[xx * 25 + ch];
        }
    }
    __syncthreads();

    {
        const int jj = tid >> 5;
        const int cc = tid & 31;
        ull s0 = 0, s1 = 0, s2 = 0;
        const ull* xp = (const ull*)buf;
        #pragma unroll 4
        for (int t = 0; t < 128; t++) {
            ull xv = xp[t * 32 + cc];
            float ka = k_s[t * 25 + jj * 3 + 0];
            float kb = k_s[t * 25 + jj * 3 + 1];
            float kc = k_s[t * 25 + jj * 3 + 2];
            fma2(s0, pack2(ka, ka), xv);
            fma2(s1, pack2(kb, kb), xv);
            fma2(s2, pack2(kc, kc), xv);
        }
        float lo, hi;
        float* Sg = g_SW + b * 1536;
        unpack2(s0, lo, hi);
        atomicAdd(&Sg[(jj * 3 + 0) * 64 + cc * 2], lo);
        atomicAdd(&Sg[(jj * 3 + 0) * 64 + cc * 2 + 1], hi);
        unpack2(s1, lo, hi);
        atomicAdd(&Sg[(jj * 3 + 1) * 64 + cc * 2], lo);
        atomicAdd(&Sg[(jj * 3 + 1) * 64 + cc * 2 + 1], hi);
        unpack2(s2, lo, hi);
        atomicAdd(&Sg[(jj * 3 + 2) * 64 + cc * 2], lo);
        atomicAdd(&Sg[(jj * 3 + 2) * 64 + cc * 2 + 1], hi);
    }
}

// ===========================================================================
// K2: per-head attention + W2. grid (8) block 256.
// ===========================================================================
__global__ __launch_bounds__(256) void k2_attn_W2(
    const float* __restrict__ Wq, const float* __restrict__ Wv,
    const float* __restrict__ Wp, const float* __restrict__ rescale)
{
    __shared__ __align__(16) float wqv_s[64 * 65];
    __shared__ float s_S[4 * 3 * 64];
    __shared__ float s_A[4 * 3 * 64];
    __shared__ float s_M[4 * 64 * 3];
    __shared__ float wp_s[3 * 24];

    const int h = blockIdx.x;
    const int tid = threadIdx.x;

    for (int i = tid; i < 4096; i += 256) {
        int c = i >> 6, d = i & 63;
        wqv_s[c * 65 + d] = Wq[c * 512 + h * 64 + d];
    }
    for (int i = tid; i < 768; i += 256) {
        int b = i / 192, rem = i - b * 192;
        s_S[i] = g_SW[b * 1536 + h * 3 * 64 + rem];
    }
    if (tid < 72) {
        int k = tid / 24, o = tid - k * 24;
        wp_s[tid] = Wp[(k * 8 + h) * 24 + o];
    }
    __syncthreads();

    const int b = tid >> 6;
    const int d = tid & 63;
    const float sc = rescale[h] * 0.125f;

    {
        float a0 = 0.f, a1 = 0.f, a2 = 0.f;
        const float* Sb = s_S + b * 192;
        #pragma unroll 8
        for (int c = 0; c < 64; c++) {
            float wq = wqv_s[c * 65 + d];
            a0 += Sb[c] * wq;
            a1 += Sb[64 + c] * wq;
            a2 += Sb[128 + c] * wq;
        }
        s_A[(b * 3 + 0) * 64 + d] = a0 * sc;
        s_A[(b * 3 + 1) * 64 + d] = a1 * sc;
        s_A[(b * 3 + 2) * 64 + d] = a2 * sc;
    }
    __syncthreads();

    {
        const int wid = tid >> 5, lane = tid & 31;
        for (int rowi = wid; rowi < 12; rowi += 8) {
            float v0 = s_A[rowi * 64 + lane];
            float v1 = s_A[rowi * 64 + 32 + lane];
            float m = fmaxf(v0, v1);
            #pragma unroll
            for (int off = 16; off; off >>= 1) m = fmaxf(m, __shfl_xor_sync(~0u, m, off));
            float e0 = __expf(v0 - m), e1 = __expf(v1 - m);
            float s = e0 + e1;
            #pragma unroll
            for (int off = 16; off; off >>= 1) s += __shfl_xor_sync(~0u, s, off);
            float inv = 1.0f / s;
            s_A[rowi * 64 + lane] = e0 * inv;
            s_A[rowi * 64 + 32 + lane] = e1 * inv;
        }
    }
    __syncthreads();

    for (int i = tid; i < 4096; i += 256) {
        int c = i >> 6, dd = i & 63;
        wqv_s[c * 65 + dd] = Wv[c * 512 + h * 64 + dd];
    }
    __syncthreads();

    {
        const int c = tid & 63;
        float m0 = 0.f, m1 = 0.f, m2 = 0.f;
        const float* Ab = s_A + b * 192;
        const float* wvr = wqv_s + c * 65;
        #pragma unroll 8
        for (int dd = 0; dd < 64; dd++) {
            float wv = wvr[dd];
            m0 += wv * Ab[dd];
            m1 += wv * Ab[64 + dd];
            m2 += wv * Ab[128 + dd];
        }
        s_M[(b * 64 + c) * 3 + 0] = m0;
        s_M[(b * 64 + c) * 3 + 1] = m1;
        s_M[(b * 64 + c) * 3 + 2] = m2;
    }
    __syncthreads();

    {
        const int c = tid & 63;
        const float* mrow = &s_M[(b * 64 + c) * 3];
        float m0 = mrow[0], m1 = mrow[1], m2 = mrow[2];
        float* W2g = g_SW + 6144 + b * 1536 + c * 24;
        #pragma unroll
        for (int o = 0; o < 24; o++) {
            float v = m0 * wp_s[o] + m1 * wp_s[24 + o] + m2 * wp_s[48 + o];
            atomicAdd(&W2g[o], v);
        }
    }
}

// ===========================================================================
// K4A: conv1 + GELU -> g_t1 (planar, exact once per pixel).
// grid (64, B): 2 image rows per block; block 192.
// smem: staged input rows [24ch][4rows][132 padded] = 50688 B.
// thread = (yloc 2, ocq 6, xseg 16): 4 out-channels x 8 px via f32x2.
// ===========================================================================
#define K4A_SMEM (12672 * 4)

__global__ __launch_bounds__(192) void k4a_conv1(const float* __restrict__ dummy)
{
    extern __shared__ __align__(16) float s[];
    const int tid = threadIdx.x;
    const int b = blockIdx.y;
    const int y0 = blockIdx.x * 2;

    for (int idx = tid; idx < 12672; idx += 192) {
        int ch = idx / 528, rem = idx - ch * 528;
        int r = rem / 132, px = rem - r * 132;
        int gy = y0 - 1 + r, gx = px - 1;
        float v = 0.f;
        if ((unsigned)gy < (unsigned)H && (unsigned)gx < (unsigned)W)
            v = g_kinp[(((size_t)b * 24 + ch) * H + gy) * W + gx];
        s[idx] = v;
    }
    __syncthreads();

    const int yloc = tid / 96;
    const int rem = tid - yloc * 96;
    const int ocq = rem / 16;
    const int xseg = rem - ocq * 16;
    const int oc0 = ocq * 4;
    const int g = oc0 >> 3;

    ull acc[16];
    #pragma unroll
    for (int m = 0; m < 16; m++) acc[m] = 0ull;

    const float* kb = s + g * 8 * 528 + yloc * 132 + xseg * 8;
    #pragma unroll
    for (int i = 0; i < 8; i++) {
        #pragma unroll
        for (int ky = 0; ky < 3; ky++) {
            const float4* rp = (const float4*)(kb + i * 528 + ky * 132);
            float4 a0 = rp[0], a1 = rp[1], a2 = rp[2];
            float w[12] = {a0.x, a0.y, a0.z, a0.w, a1.x, a1.y, a1.z, a1.w,
                           a2.x, a2.y, a2.z, a2.w};
            ull sj[10];
            #pragma unroll
            for (int j = 0; j < 10; j++) sj[j] = pack2(w[j], w[j]);
            #pragma unroll
            for (int kx = 0; kx < 3; kx++) {
                const ulonglong2 wv = *(const ulonglong2*)
                    &g_wt[0][(i * 9 + ky * 3 + kx) * 24 + oc0];
                #pragma unroll
                for (int o = 0; o < 8; o++) {
                    fma2(acc[o * 2], wv.x, sj[o + kx]);
                    fma2(acc[o * 2 + 1], wv.y, sj[o + kx]);
                }
            }
        }
    }

    // gelu + planar store: 4 oc-rows x 8 px
    float vals[4][8];
    #pragma unroll
    for (int o = 0; o < 8; o++) {
        float v0, v1, v2, v3;
        unpack2(acc[o * 2], v0, v1);
        unpack2(acc[o * 2 + 1], v2, v3);
        vals[0][o] = gelu_exact(v0);
        vals[1][o] = gelu_exact(v1);
        vals[2][o] = gelu_exact(v2);
        vals[3][o] = gelu_exact(v3);
    }
    #pragma unroll
    for (int u = 0; u < 4; u++) {
        float4* dst = (float4*)(g_t1 +
            (((size_t)b * 24 + oc0 + u) * H + (y0 + yloc)) * W + xseg * 8);
        dst[0] = make_float4(vals[u][0], vals[u][1], vals[u][2], vals[u][3]);
        dst[1] = make_float4(vals[u][4], vals[u][5], vals[u][6], vals[u][7]);
    }
}

// ===========================================================================
// K4B: conv2 (from g_t1) + projection fea@W2+bp + final store.
// grid (64, B): 2 rows per block; block 256.
// smem (floats): t1s[12672] c2s[6144] W2s[1536] bps[32] = 81536 B.
// ===========================================================================
#define K4B_T1S 0
#define K4B_C2S 12672
#define K4B_W2S 18816
#define K4B_BPS 20352
#define K4B_SMEM ((20352 + 32) * 4)

__global__ __launch_bounds__(256) void k4b_conv2_proj(
    const float* __restrict__ fea, const float* __restrict__ bp,
    float* __restrict__ out)
{
    extern __shared__ __align__(16) float s[];
    float* t1s = s + K4B_T1S;
    float* c2s = s + K4B_C2S;   // [oc][2][128]
    float* W2s = s + K4B_W2S;
    float* bps = s + K4B_BPS;

    const int tid = threadIdx.x;
    const int b = blockIdx.y;
    const int y0 = blockIdx.x * 2;

    for (int idx = tid; idx < 12672; idx += 256) {
        int ch = idx / 528, rem = idx - ch * 528;
        int r = rem / 132, px = rem - r * 132;
        int gy = y0 - 1 + r, gx = px - 1;
        float v = 0.f;
        if ((unsigned)gy < (unsigned)H && (unsigned)gx < (unsigned)W)
            v = g_t1[(((size_t)b * 24 + ch) * H + gy) * W + gx];
        t1s[idx] = v;
    }
    {
        const float* w2g = g_SW + 6144 + b * 1536;
        for (int i = tid; i < 1536; i += 256) W2s[i] = w2g[i];
    }
    if (tid < 24) bps[tid] = bp[tid];
    __syncthreads();

    if (tid < 192) {
        const int yloc = tid / 96;
        const int rem = tid - yloc * 96;
        const int ocq = rem / 16;
        const int xseg = rem - ocq * 16;
        const int oc0 = ocq * 4;
        const int g = oc0 >> 3;

        ull acc[16];
        #pragma unroll
        for (int m = 0; m < 16; m++) acc[m] = 0ull;

        const float* kb = t1s + g * 8 * 528 + yloc * 132 + xseg * 8;
        #pragma unroll
        for (int i = 0; i < 8; i++) {
            #pragma unroll
            for (int ky = 0; ky < 3; ky++) {
                const float4* rp = (const float4*)(kb + i * 528 + ky * 132);
                float4 a0 = rp[0], a1 = rp[1], a2 = rp[2];
                float w[12] = {a0.x, a0.y, a0.z, a0.w, a1.x, a1.y, a1.z, a1.w,
                               a2.x, a2.y, a2.z, a2.w};
                ull sj[10];
                #pragma unroll
                for (int j = 0; j < 10; j++) sj[j] = pack2(w[j], w[j]);
                #pragma unroll
                for (int kx = 0; kx < 3; kx++) {
                    const ulonglong2 wv = *(const ulonglong2*)
                        &g_wt[1][(i * 9 + ky * 3 + kx) * 24 + oc0];
                    #pragma unroll
                    for (int o = 0; o < 8; o++) {
                        fma2(acc[o * 2], wv.x, sj[o + kx]);
                        fma2(acc[o * 2 + 1], wv.y, sj[o + kx]);
                    }
                }
            }
        }
        #pragma unroll
        for (int o = 0; o < 8; o++) {
            float v0, v1, v2, v3;
            unpack2(acc[o * 2], v0, v1);
            unpack2(acc[o * 2 + 1], v2, v3);
            int xb = xseg * 8 + o;
            c2s[((oc0 + 0) * 2 + yloc) * 128 + xb] = v0;
            c2s[((oc0 + 1) * 2 + yloc) * 128 + xb] = v1;
            c2s[((oc0 + 2) * 2 + yloc) * 128 + xb] = v2;
            c2s[((oc0 + 3) * 2 + yloc) * 128 + xb] = v3;
        }
    }
    __syncthreads();

    // projection: one pixel per thread (2 rows x 128 px)
    {
        const int yy = tid >> 7;
        const int px = tid & 127;
        ull acc[12];
        #pragma unroll
        for (int m = 0; m < 12; m++) acc[m] = 0ull;
        const float4* fea4 = (const float4*)(fea +
            ((size_t)b * NTOK + (size_t)(y0 + yy) * W + px) * 64);
        #pragma unroll 4
        for (int c4 = 0; c4 < 16; c4++) {
            float4 f = fea4[c4];
            float fe[4] = {f.x, f.y, f.z, f.w};
            #pragma unroll
            for (int e = 0; e < 4; e++) {
                ull f2 = pack2(fe[e], fe[e]);
                const ulonglong2* wrow =
                    (const ulonglong2*)&W2s[(c4 * 4 + e) * 24];
                #pragma unroll
                for (int m = 0; m < 6; m++) {
                    ulonglong2 wp = wrow[m];
                    fma2(acc[2 * m], wp.x, f2);
                    fma2(acc[2 * m + 1], wp.y, f2);
                }
            }
        }
        float res[24];
        #pragma unroll
        for (int m = 0; m < 12; m++) {
            float lo, hi; unpack2(acc[m], lo, hi);
            res[2 * m] = lo + bps[2 * m];
            res[2 * m + 1] = hi + bps[2 * m + 1];
        }
        #pragma unroll
        for (int ch = 0; ch < 24; ch++)
            res[ch] += c2s[(ch * 2 + yy) * 128 + px];
        float4* og = (float4*)(out +
            ((size_t)b * NTOK + (size_t)(y0 + yy) * W + px) * 24);
        #pragma unroll
        for (int q = 0; q < 6; q++)
            og[q] = make_float4(res[q * 4], res[q * 4 + 1],
                                res[q * 4 + 2], res[q * 4 + 3]);
    }
}

// ===========================================================================
extern "C" void kernel_launch(void* const* d_in, const int* in_sizes, int n_in,
                              void* d_out, int out_size)
{
    const float* x = (const float*)d_in[0];
    const float* fea = (const float*)d_in[1];
    const float* im = (const float*)d_in[2];
    const float* Wq = (const float*)d_in[3];
    const float* Wk = (const float*)d_in[4];
    const float* Wv = (const float*)d_in[5];
    const float* rescale = (const float*)d_in[6];
    const float* Wp = (const float*)d_in[7];
    const float* bp = (const float*)d_in[8];
    const float* c1w = (const float*)d_in[9];
    const float* c2w = (const float*)d_in[10];
    float* out = (float*)d_out;

    cudaFuncSetAttribute(k4a_conv1,
                         cudaFuncAttributeMaxDynamicSharedMemorySize, K4A_SMEM);
    cudaFuncSetAttribute(k4b_conv2_proj,
                         cudaFuncAttributeMaxDynamicSharedMemorySize, K4B_SMEM);

    kwt_prep<<<1, 256>>>(c1w, c2w);                       // launch 0
    k1_kinp_S<<<dim3(128, B), 256>>>(x, im, Wk);          // launch 1
    k2_attn_W2<<<dim3(HEADS), 256>>>(Wq, Wv, Wp, rescale);// launch 2
    k4a_conv1<<<dim3(64, B), 192, K4A_SMEM>>>(nullptr);   // launch 3
    k4b_conv2_proj<<<dim3(64, B), 256, K4B_SMEM>>>(fea, bp, out); // launch 4
}